// round 16
// baseline (speedup 1.0000x reference)
#include <cuda_runtime.h>

// Problem constants (fixed by the dataset)
#define C_CH    192
#define TOTAL4  (3072 * 1024)   // B*C*H*W / 4 float4s
#define THREADS 256
#define GRID_X  740             // 5 * 148 SMs: exactly 5 blocks/SM, one even wave

__device__ __forceinline__ float softplus_acc(float x) {
    return (x > 20.0f) ? x : log1pf(expf(x));
}

__device__ __forceinline__ float ex2_approx(float x) {
    float y;
    asm("ex2.approx.f32 %0, %1;" : "=f"(y) : "f"(x));
    return y;
}

__device__ __forceinline__ float rcp_approx(float x) {
    float y;
    asm("rcp.approx.f32 %0, %1;" : "=f"(y) : "f"(x));
    return y;
}

// Flat-range kernel: every block builds the full 192-channel constant table in
// shared memory, then streams an even 1/740 share of the element space.
// Loads: default caching (input stays L2-resident across graph replays).
// Stores: evict-first (.cs) — output has zero reuse.
__global__ __launch_bounds__(THREADS, 5)
void ent_flat_kernel(const float4* __restrict__ x4, float4* __restrict__ o4,
                     const float* __restrict__ m0p, const float* __restrict__ m1p,
                     const float* __restrict__ m2p, const float* __restrict__ m3p,
                     const float* __restrict__ b0p, const float* __restrict__ b1p,
                     const float* __restrict__ b2p, const float* __restrict__ b3p,
                     const float* __restrict__ f0p, const float* __restrict__ f1p,
                     const float* __restrict__ f2p) {
    __shared__ float4 SP4[C_CH];        // na, nb, dd, kk
    __shared__ float  SP1[C_CH];        // kp1
    __shared__ float  AFF[C_CH];        // affine flag per channel
    __shared__ float  Wg [C_CH * 24];   // softplus'd weights (fallback)
    __shared__ float  TFg[C_CH * 9];    // tanh(factor)      (fallback)
    __shared__ float  BIg[C_CH * 10];   // biases            (fallback)

    const int tid = threadIdx.x;

    // ---- prologue: thread t < 192 builds channel t's tables ----
    if (tid < C_CH) {
        const int c = tid;
        float* Wc  = Wg  + c * 24;
        float* TFc = TFg + c * 9;
        float* BIc = BIg + c * 10;

        #pragma unroll
        for (int j = 0; j < 3; j++)  Wc[j]      = softplus_acc(m0p[c * 3 + j]);
        #pragma unroll
        for (int j = 0; j < 9; j++)  Wc[3 + j]  = softplus_acc(m1p[c * 9 + j]);
        #pragma unroll
        for (int j = 0; j < 9; j++)  Wc[12 + j] = softplus_acc(m2p[c * 9 + j]);
        #pragma unroll
        for (int j = 0; j < 3; j++)  Wc[21 + j] = softplus_acc(m3p[c * 3 + j]);

        bool affine = true;
        #pragma unroll
        for (int j = 0; j < 3; j++) {
            TFc[j]     = tanhf(f0p[c * 3 + j]);
            TFc[3 + j] = tanhf(f1p[c * 3 + j]);
            TFc[6 + j] = tanhf(f2p[c * 3 + j]);
        }
        #pragma unroll
        for (int j = 0; j < 9; j++) affine = affine && (TFc[j] == 0.0f);

        #pragma unroll
        for (int j = 0; j < 3; j++) {
            BIc[j]     = b0p[c * 3 + j];
            BIc[3 + j] = b1p[c * 3 + j];
            BIc[6 + j] = b2p[c * 3 + j];
        }
        BIc[9] = b3p[c];

        // slope A = m3 . M2 . M1 . m0
        float d1[3], d2[3];
        #pragma unroll
        for (int i = 0; i < 3; i++)
            d1[i] = Wc[3+i*3+0]*Wc[0] + Wc[3+i*3+1]*Wc[1] + Wc[3+i*3+2]*Wc[2];
        #pragma unroll
        for (int i = 0; i < 3; i++)
            d2[i] = Wc[12+i*3+0]*d1[0] + Wc[12+i*3+1]*d1[1] + Wc[12+i*3+2]*d1[2];
        float A = Wc[21]*d2[0] + Wc[22]*d2[1] + Wc[23]*d2[2];
        // intercept beta = chain(0): biases only
        float h1[3], h2[3];
        #pragma unroll
        for (int i = 0; i < 3; i++)
            h1[i] = Wc[3+i*3+0]*BIc[0] + Wc[3+i*3+1]*BIc[1] + Wc[3+i*3+2]*BIc[2] + BIc[3+i];
        #pragma unroll
        for (int i = 0; i < 3; i++)
            h2[i] = Wc[12+i*3+0]*h1[0] + Wc[12+i*3+1]*h1[1] + Wc[12+i*3+2]*h1[2] + BIc[6+i];
        float beta = Wc[21]*h2[0] + Wc[22]*h2[1] + Wc[23]*h2[2] + BIc[9];

        const float LOG2E = 1.4426950408889634f;
        float B1 = fmaf(0.5f, A, beta);
        float ek = expm1f(A);                       // e^A - 1 > 0
        SP4[c] = make_float4(-A * LOG2E,            // na
                             -B1 * LOG2E,           // nb
                             ek,                    // dd = e^A - 1
                             ek + 1.0f);            // kk = e^A
        SP1[c] = ek + 2.0f;                         // kp1 = 1 + e^A
        AFF[c] = affine ? 1.0f : 0.0f;
    }
    __syncthreads();

    // ---- main loop: flat even share of the float4 space ----
    const int bid   = blockIdx.x;
    const int start = (int)(((long long)bid       * TOTAL4) / GRID_X);
    const int end   = (int)(((long long)(bid + 1) * TOTAL4) / GRID_X);

    // generic layered chain (fallback), reading channel tables from shared
    auto chain = [&](float t, int c) -> float {
        const float* Wc  = Wg  + c * 24;
        const float* TFc = TFg + c * 9;
        const float* BIc = BIg + c * 10;
        float h[3], g[3];
        #pragma unroll
        for (int j = 0; j < 3; j++) {
            h[j] = fmaf(Wc[j], t, BIc[j]);
            h[j] = fmaf(TFc[j], tanhf(h[j]), h[j]);
        }
        #pragma unroll
        for (int i = 0; i < 3; i++) {
            g[i] = fmaf(Wc[3+i*3+0], h[0], fmaf(Wc[3+i*3+1], h[1],
                   fmaf(Wc[3+i*3+2], h[2], BIc[3+i])));
            g[i] = fmaf(TFc[3+i], tanhf(g[i]), g[i]);
        }
        #pragma unroll
        for (int i = 0; i < 3; i++) {
            h[i] = fmaf(Wc[12+i*3+0], g[0], fmaf(Wc[12+i*3+1], g[1],
                   fmaf(Wc[12+i*3+2], g[2], BIc[6+i])));
            h[i] = fmaf(TFc[6+i], tanhf(h[i]), h[i]);
        }
        return fmaf(Wc[21], h[0], fmaf(Wc[22], h[1], fmaf(Wc[23], h[2], BIc[9])));
    };

    auto process = [&](int idx, float4 v) {
        const int c = (idx >> 10) % C_CH;     // slab = idx/1024; channel = slab%192
        float4 r;
        const float* vp = &v.x;
        float* rp = &r.x;
        if (AFF[c] != 0.0f) {
            const float4 p  = SP4[c];
            const float kp1 = SP1[c];
            #pragma unroll
            for (int e = 0; e < 4; e++) {
                const float t    = ex2_approx(fmaf(p.x, vp[e], p.y));   // e^{-U}
                const float den  = fmaf(t, fmaf(t, p.w, kp1), 1.0f);
                const float like = (t * p.z) * rcp_approx(den);
                rp[e] = fmaxf(like, 1e-6f);
            }
        } else {
            #pragma unroll
            for (int e = 0; e < 4; e++) {
                const float L = chain(vp[e] - 0.5f, c);
                const float U = chain(vp[e] + 0.5f, c);
                const float sum = L + U;
                const float sgn = (sum > 0.0f) ? -1.0f : ((sum < 0.0f) ? 1.0f : 0.0f);
                const float a  = fminf(sgn * U, 80.0f);
                const float bb = fminf(sgn * L, 80.0f);
                const float sa = __fdividef(1.0f, 1.0f + __expf(-a));
                const float sb = __fdividef(1.0f, 1.0f + __expf(-bb));
                rp[e] = fmaxf(fabsf(sa - sb), 1e-6f);
            }
        }
        __stcs(&o4[idx], r);
    };

    int i = start + tid;
    // 4-batched main loop (MLP = 4)
    for (; i + 3 * THREADS < end; i += 4 * THREADS) {
        float4 v[4];
        #pragma unroll
        for (int k = 0; k < 4; k++)
            v[k] = x4[i + k * THREADS];
        #pragma unroll
        for (int k = 0; k < 4; k++)
            process(i + k * THREADS, v[k]);
    }
    // remainder
    for (; i < end; i += THREADS)
        process(i, x4[i]);
}

extern "C" void kernel_launch(void* const* d_in, const int* in_sizes, int n_in,
                              void* d_out, int out_size) {
    const float* x = (const float*)d_in[0];
    const float *m0, *m1, *m2, *m3, *b0, *b1, *b2, *b3, *f0, *f1, *f2;

    // Disambiguate input ordering by element counts:
    //   matrix_1 / matrix_2 are the only 1728-element tensors.
    if (n_in >= 12 && in_sizes[4] == 1728) {
        m0 = (const float*)d_in[1];  b0 = (const float*)d_in[2];  f0 = (const float*)d_in[3];
        m1 = (const float*)d_in[4];  b1 = (const float*)d_in[5];  f1 = (const float*)d_in[6];
        m2 = (const float*)d_in[7];  b2 = (const float*)d_in[8];  f2 = (const float*)d_in[9];
        m3 = (const float*)d_in[10]; b3 = (const float*)d_in[11];
    } else {
        m0 = (const float*)d_in[1];  m1 = (const float*)d_in[2];
        m2 = (const float*)d_in[3];  m3 = (const float*)d_in[4];
        b0 = (const float*)d_in[5];  b1 = (const float*)d_in[6];
        b2 = (const float*)d_in[7];  b3 = (const float*)d_in[8];
        f0 = (const float*)d_in[9];  f1 = (const float*)d_in[10]; f2 = (const float*)d_in[11];
    }

    ent_flat_kernel<<<GRID_X, THREADS>>>((const float4*)x, (float4*)d_out,
                                         m0, m1, m2, m3, b0, b1, b2, b3,
                                         f0, f1, f2);
}

// round 17
// speedup vs baseline: 2.3807x; 2.3807x over previous
#include <cuda_runtime.h>

// Problem constants (fixed by the dataset)
#define C_CH    192
#define HW4     1024         // float4s per (b,c) slab (64*64/4)
#define THREADS 128
#define NB      2            // slabs (batches) per block
#define GRID_Y  8            // 16 batches / NB  -> grid 192*8 = 1536 blocks
// __launch_bounds__(128, 12): cap 42 regs -> 12 blocks/SM -> 1776 capacity:
// one wave; per-SM split 10 vs 11 (~6% imbalance vs 15.6% at 256thr/768).

__device__ __forceinline__ float softplus_acc(float x) {
    return (x > 20.0f) ? x : log1pf(expf(x));   // accurate: weights compound 4 layers
}

__device__ __forceinline__ float ex2_approx(float x) {
    float y;
    asm("ex2.approx.f32 %0, %1;" : "=f"(y) : "f"(x));
    return y;
}

__device__ __forceinline__ float rcp_approx(float x) {
    float y;
    asm("rcp.approx.f32 %0, %1;" : "=f"(y) : "f"(x));
    return y;
}

// Fused kernel, grid (C_CH, GRID_Y): block (c, y) derives channel-c constants
// once (distributed across threads), then streams slabs for batches
// {NB*y .. NB*y+NB-1}.
// Loads: default caching (input stays L2-resident across graph replays).
// Stores: evict-first (.cs) — output has zero reuse.
__global__ __launch_bounds__(THREADS, 12)
void ent_fused_kernel(const float4* __restrict__ x4, float4* __restrict__ o4,
                      const float* __restrict__ m0p, const float* __restrict__ m1p,
                      const float* __restrict__ m2p, const float* __restrict__ m3p,
                      const float* __restrict__ b0p, const float* __restrict__ b1p,
                      const float* __restrict__ b2p, const float* __restrict__ b3p,
                      const float* __restrict__ f0p, const float* __restrict__ f1p,
                      const float* __restrict__ f2p) {
    __shared__ float W[24];    // sm0[0..2], M1[3..11], M2[12..20], sm3[21..23]
    __shared__ float TF[9];    // tanh(factor)
    __shared__ float BI[10];   // b0, b1, b2, b3
    __shared__ float CC[5];    // na, nb, dd, kk, kp1
    __shared__ float AFF[1];   // affine flag

    const int c   = blockIdx.x;
    const int tid = threadIdx.x;

    // ---- prologue: distributed transcendentals (accurate softplus/tanh) ----
    if (tid < 24) {
        float v;
        if (tid < 3)       v = m0p[c * 3 + tid];
        else if (tid < 12) v = m1p[c * 9 + (tid - 3)];
        else if (tid < 21) v = m2p[c * 9 + (tid - 12)];
        else               v = m3p[c * 3 + (tid - 21)];
        W[tid] = softplus_acc(v);
    } else if (tid >= 32 && tid < 41) {
        int j = tid - 32;
        float f = (j < 3) ? f0p[c * 3 + j] : (j < 6) ? f1p[c * 3 + (j - 3)]
                                           : f2p[c * 3 + (j - 6)];
        TF[j] = tanhf(f);
    } else if (tid >= 64 && tid < 74) {
        int j = tid - 64;
        BI[j] = (j < 3) ? b0p[c * 3 + j] : (j < 6) ? b1p[c * 3 + (j - 3)]
              : (j < 9) ? b2p[c * 3 + (j - 6)] : b3p[c];
    }
    __syncthreads();

    if (tid == 0) {
        const float* sm0 = W;
        const float* M1  = W + 3;
        const float* M2  = W + 12;
        const float* sm3 = W + 21;
        // slope A = m3 . M2 . M1 . m0
        float d1[3], d2[3];
        #pragma unroll
        for (int i = 0; i < 3; i++)
            d1[i] = M1[i*3+0]*sm0[0] + M1[i*3+1]*sm0[1] + M1[i*3+2]*sm0[2];
        #pragma unroll
        for (int i = 0; i < 3; i++)
            d2[i] = M2[i*3+0]*d1[0] + M2[i*3+1]*d1[1] + M2[i*3+2]*d1[2];
        float A = sm3[0]*d2[0] + sm3[1]*d2[1] + sm3[2]*d2[2];
        // intercept beta = chain(0): biases only
        float h1[3], h2[3];
        #pragma unroll
        for (int i = 0; i < 3; i++)
            h1[i] = M1[i*3+0]*BI[0] + M1[i*3+1]*BI[1] + M1[i*3+2]*BI[2] + BI[3+i];
        #pragma unroll
        for (int i = 0; i < 3; i++)
            h2[i] = M2[i*3+0]*h1[0] + M2[i*3+1]*h1[1] + M2[i*3+2]*h1[2] + BI[6+i];
        float beta = sm3[0]*h2[0] + sm3[1]*h2[1] + sm3[2]*h2[2] + BI[9];

        bool affine = true;
        #pragma unroll
        for (int j = 0; j < 9; j++) affine = affine && (TF[j] == 0.0f);

        // U(x) = A*x + B1,  B1 = beta + A/2;  t = e^{-U} = 2^(na*x+nb)
        // like = t*d / (1 + t*(1+k) + t^2*k) = (t*d) * rcp(fma(t, fma(t,k,1+k), 1))
        const float LOG2E = 1.4426950408889634f;
        float B1 = fmaf(0.5f, A, beta);
        float ek = expm1f(A);           // e^A - 1 > 0
        CC[0] = -A * LOG2E;             // na
        CC[1] = -B1 * LOG2E;            // nb
        CC[2] = ek;                     // dd = e^A - 1
        CC[3] = ek + 1.0f;              // kk = e^A
        CC[4] = ek + 2.0f;              // kp1 = 1 + e^A
        AFF[0] = affine ? 1.0f : 0.0f;
    }
    __syncthreads();

    if (AFF[0] != 0.0f) {
        // ------- collapsed affine fast path: ~8 instr/element -------
        const float na = CC[0], nb = CC[1], dd = CC[2], kk = CC[3], kp1 = CC[4];

        #pragma unroll
        for (int s = 0; s < NB; s++) {
            const int base = ((NB * blockIdx.y + s) * C_CH + c) * HW4;
            #pragma unroll
            for (int p = 0; p < 2; p++) {
                float4 v[4];
                #pragma unroll
                for (int k = 0; k < 4; k++)
                    v[k] = x4[base + tid + (p * 4 + k) * THREADS];

                #pragma unroll
                for (int k = 0; k < 4; k++) {
                    float4 r;
                    const float* vp = &v[k].x;
                    float* rp = &r.x;
                    #pragma unroll
                    for (int e = 0; e < 4; e++) {
                        const float t   = ex2_approx(fmaf(na, vp[e], nb));   // e^{-U}
                        const float den = fmaf(t, fmaf(t, kk, kp1), 1.0f);
                        const float like = (t * dd) * rcp_approx(den);
                        rp[e] = fmaxf(like, 1e-6f);
                    }
                    __stcs(&o4[base + tid + (p * 4 + k) * THREADS], r);
                }
            }
        }
        return;
    }

    // ------- generic layered fallback (non-affine factors) -------
    {
        const float b3 = BI[9];
        auto chain = [&](float t) -> float {
            float h[3], g[3];
            #pragma unroll
            for (int j = 0; j < 3; j++) {
                h[j] = fmaf(W[j], t, BI[j]);
                h[j] = fmaf(TF[j], tanhf(h[j]), h[j]);
            }
            #pragma unroll
            for (int i = 0; i < 3; i++) {
                g[i] = fmaf(W[3+i*3+0], h[0], fmaf(W[3+i*3+1], h[1],
                       fmaf(W[3+i*3+2], h[2], BI[3+i])));
                g[i] = fmaf(TF[3+i], tanhf(g[i]), g[i]);
            }
            #pragma unroll
            for (int i = 0; i < 3; i++) {
                h[i] = fmaf(W[12+i*3+0], g[0], fmaf(W[12+i*3+1], g[1],
                       fmaf(W[12+i*3+2], g[2], BI[6+i])));
                h[i] = fmaf(TF[6+i], tanhf(h[i]), h[i]);
            }
            return fmaf(W[21], h[0], fmaf(W[22], h[1], fmaf(W[23], h[2], b3)));
        };

        for (int s = 0; s < NB; s++) {
            const int base = ((NB * blockIdx.y + s) * C_CH + c) * HW4;
            #pragma unroll
            for (int k = 0; k < 8; k++) {
                const int idx = base + tid + k * THREADS;
                float4 v = x4[idx];
                float4 r;
                const float* vp = &v.x;
                float* rp = &r.x;
                #pragma unroll
                for (int e = 0; e < 4; e++) {
                    const float L = chain(vp[e] - 0.5f);
                    const float U = chain(vp[e] + 0.5f);
                    const float sum = L + U;
                    const float sgn = (sum > 0.0f) ? -1.0f : ((sum < 0.0f) ? 1.0f : 0.0f);
                    const float a  = fminf(sgn * U, 80.0f);
                    const float bb = fminf(sgn * L, 80.0f);
                    const float sa = __fdividef(1.0f, 1.0f + __expf(-a));
                    const float sb = __fdividef(1.0f, 1.0f + __expf(-bb));
                    rp[e] = fmaxf(fabsf(sa - sb), 1e-6f);
                }
                __stcs(&o4[idx], r);
            }
        }
    }
}

extern "C" void kernel_launch(void* const* d_in, const int* in_sizes, int n_in,
                              void* d_out, int out_size) {
    const float* x = (const float*)d_in[0];
    const float *m0, *m1, *m2, *m3, *b0, *b1, *b2, *b3, *f0, *f1, *f2;

    // Disambiguate input ordering by element counts:
    //   matrix_1 / matrix_2 are the only 1728-element tensors.
    if (n_in >= 12 && in_sizes[4] == 1728) {
        m0 = (const float*)d_in[1];  b0 = (const float*)d_in[2];  f0 = (const float*)d_in[3];
        m1 = (const float*)d_in[4];  b1 = (const float*)d_in[5];  f1 = (const float*)d_in[6];
        m2 = (const float*)d_in[7];  b2 = (const float*)d_in[8];  f2 = (const float*)d_in[9];
        m3 = (const float*)d_in[10]; b3 = (const float*)d_in[11];
    } else {
        m0 = (const float*)d_in[1];  m1 = (const float*)d_in[2];
        m2 = (const float*)d_in[3];  m3 = (const float*)d_in[4];
        b0 = (const float*)d_in[5];  b1 = (const float*)d_in[6];
        b2 = (const float*)d_in[7];  b3 = (const float*)d_in[8];
        f0 = (const float*)d_in[9];  f1 = (const float*)d_in[10]; f2 = (const float*)d_in[11];
    }

    dim3 grid(C_CH, GRID_Y);
    ent_fused_kernel<<<grid, THREADS>>>((const float4*)x, (float4*)d_out,
                                        m0, m1, m2, m3, b0, b1, b2, b3, f0, f1, f2);
}